// round 17
// baseline (speedup 1.0000x reference)
#include <cuda_runtime.h>
#include <cuda_bf16.h>
#include <cstdint>

#define Bn 256
#define Tn 256
#define Cn 256
#define Hn 64

// ---------------- scratch ----------------
__device__ __align__(16) __nv_bfloat16 g_qh[Bn*Tn*Hn];
__device__ __align__(16) __nv_bfloat16 g_ql[Bn*Tn*Hn];
__device__ __align__(16) __nv_bfloat16 g_kh[Bn*Tn*Hn];
__device__ __align__(16) __nv_bfloat16 g_kl[Bn*Tn*Hn];
__device__ __align__(16) __nv_bfloat16 g_vh[Bn*Tn*Hn];
__device__ __align__(16) __nv_bfloat16 g_vl[Bn*Tn*Hn];
__device__ __align__(16) __nv_bfloat16 g_Wh[4*192*72];
__device__ __align__(16) __nv_bfloat16 g_Wl[4*192*72];
__device__ __align__(16) __nv_bfloat16 g_Eh[256*72];
__device__ __align__(16) __nv_bfloat16 g_El[256*72];

// ---------------- helpers ----------------
__device__ __forceinline__ uint32_t smem_u32(const void* p) {
    uint32_t a;
    asm("{ .reg .u64 t; cvta.to.shared.u64 t, %1; cvt.u32.u64 %0, t; }" : "=r"(a) : "l"(p));
    return a;
}
__device__ __forceinline__ void mma_bf16(float* c, const uint32_t* a, const uint32_t* b) {
    asm volatile(
        "mma.sync.aligned.m16n8k16.row.col.f32.bf16.bf16.f32 "
        "{%0,%1,%2,%3}, {%4,%5,%6,%7}, {%8,%9}, {%0,%1,%2,%3};"
        : "+f"(c[0]), "+f"(c[1]), "+f"(c[2]), "+f"(c[3])
        : "r"(a[0]), "r"(a[1]), "r"(a[2]), "r"(a[3]), "r"(b[0]), "r"(b[1]));
}
__device__ __forceinline__ void ldsm4(uint32_t* r, uint32_t addr) {
    asm volatile("ldmatrix.sync.aligned.m8n8.x4.shared.b16 {%0,%1,%2,%3}, [%4];"
        : "=r"(r[0]), "=r"(r[1]), "=r"(r[2]), "=r"(r[3]) : "r"(addr));
}
__device__ __forceinline__ void ldsm4t(uint32_t* r, uint32_t addr) {
    asm volatile("ldmatrix.sync.aligned.m8n8.x4.trans.shared.b16 {%0,%1,%2,%3}, [%4];"
        : "=r"(r[0]), "=r"(r[1]), "=r"(r[2]), "=r"(r[3]) : "r"(addr));
}
__device__ __forceinline__ void split_bf(float v, __nv_bfloat16& h, __nv_bfloat16& l) {
    h = __float2bfloat16(v);
    l = __float2bfloat16(v - __bfloat162float(h));
}
__device__ __forceinline__ uint32_t pk(__nv_bfloat16 a, __nv_bfloat16 b) {
    return (uint32_t)__bfloat16_as_ushort(a) | ((uint32_t)__bfloat16_as_ushort(b) << 16);
}

// ---------------------------------------------------------------------------
// Setup: build hi/lo pad-72 images of [Wq|Wk*0.125|Wv] and E.
// ---------------------------------------------------------------------------
__global__ __launch_bounds__(256) void setup_kernel(
    const float* __restrict__ Wk, const float* __restrict__ Wq,
    const float* __restrict__ Wv, const float* __restrict__ E)
{
    int id = blockIdx.x * 256 + threadIdx.x;
    if (id < 4 * 192 * 72) {
        int kt = id / (192 * 72);
        int rem = id % (192 * 72);
        int n = rem / 72, k = rem % 72;
        float v = 0.f;
        if (k < 64) {
            int which = n >> 6, col = n & 63;
            const float* W = (which == 0) ? Wq : (which == 1) ? Wk : Wv;
            v = W[(kt * 64 + k) * Hn + col];
            if (which == 1) v *= 0.125f;
        }
        __nv_bfloat16 h, l;
        split_bf(v, h, l);
        g_Wh[id] = h;
        g_Wl[id] = l;
    } else {
        int id2 = id - 4 * 192 * 72;
        if (id2 < 256 * 72) {
            int d = id2 / 72, k = id2 % 72;
            float v = (k < 64) ? E[d * Hn + k] : 0.f;
            __nv_bfloat16 h, l;
            split_bf(v, h, l);
            g_Eh[id2] = h;
            g_El[id2] = l;
        }
    }
}

// ---------------------------------------------------------------------------
// Fused qkv GEMM (bf16x3, ldmatrix). grid=512, block=512. (unchanged)
// ---------------------------------------------------------------------------
__global__ __launch_bounds__(512, 1) void qkv_kernel(const float* __restrict__ x)
{
    extern __shared__ __nv_bfloat16 smb[];
    __nv_bfloat16* Ah = smb;
    __nv_bfloat16* Al = Ah + 128 * 72;
    __nv_bfloat16* Bh = Al + 128 * 72;
    __nv_bfloat16* Bl = Bh + 192 * 72;

    const int row0 = blockIdx.x * 128;
    const int tid = threadIdx.x, w = tid >> 5, lane = tid & 31;
    const int wm = w >> 2, wn = w & 3;
    const int g = lane >> 2, l2 = lane & 3;

    const uint32_t aH = smem_u32(Ah), aL = smem_u32(Al);
    const uint32_t bH = smem_u32(Bh), bL = smem_u32(Bl);
    const int arow = wm * 32 + (lane & 15);
    const int acol = (lane >> 4) * 8;
    const int brow = wn * 48 + (lane & 7) + (lane >> 4) * 8;
    const int bcol = ((lane >> 3) & 1) * 8;

    float acc[2][6][4] = {};

    for (int ct = 0; ct < 4; ct++) {
        float4 xv[4];
        #pragma unroll
        for (int i = 0; i < 4; i++) {
            int f = tid + i * 512;
            int r = f >> 4, c4 = (f & 15) << 2;
            xv[i] = *(const float4*)(x + (row0 + r) * Cn + ct * 64 + c4);
        }
        __syncthreads();

        {
            uint4* dh = (uint4*)Bh;
            uint4* dl = (uint4*)Bl;
            const uint4* sh = (const uint4*)(g_Wh + ct * 192 * 72);
            const uint4* sl = (const uint4*)(g_Wl + ct * 192 * 72);
            #pragma unroll
            for (int idx = tid; idx < 1728; idx += 512) {
                dh[idx] = sh[idx];
                dl[idx] = sl[idx];
            }
        }
        #pragma unroll
        for (int i = 0; i < 4; i++) {
            int f = tid + i * 512;
            int r = f >> 4, c4 = (f & 15) << 2;
            __nv_bfloat16 h0, l0, h1, l1, h2, l2b, h3, l3;
            split_bf(xv[i].x, h0, l0);
            split_bf(xv[i].y, h1, l1);
            split_bf(xv[i].z, h2, l2b);
            split_bf(xv[i].w, h3, l3);
            uint2 uh = {pk(h0, h1), pk(h2, h3)};
            uint2 ul = {pk(l0, l1), pk(l2b, l3)};
            *(uint2*)(Ah + r * 72 + c4) = uh;
            *(uint2*)(Al + r * 72 + c4) = ul;
        }
        __syncthreads();

        #pragma unroll
        for (int ks = 0; ks < 64; ks += 16) {
            uint32_t ah[2][4], al[2][4], bh[3][4], bl[3][4];
            #pragma unroll
            for (int mi = 0; mi < 2; mi++) {
                uint32_t off = ((arow + mi * 16) * 72 + ks + acol) * 2;
                ldsm4(ah[mi], aH + off);
                ldsm4(al[mi], aL + off);
            }
            #pragma unroll
            for (int nj = 0; nj < 3; nj++) {
                uint32_t off = ((brow + nj * 16) * 72 + ks + bcol) * 2;
                ldsm4(bh[nj], bH + off);
                ldsm4(bl[nj], bL + off);
            }
            #pragma unroll
            for (int mi = 0; mi < 2; mi++)
                #pragma unroll
                for (int ni = 0; ni < 6; ni++) {
                    const uint32_t* ph = &bh[ni >> 1][(ni & 1) * 2];
                    const uint32_t* pl = &bl[ni >> 1][(ni & 1) * 2];
                    mma_bf16(acc[mi][ni], ah[mi], ph);
                    mma_bf16(acc[mi][ni], ah[mi], pl);
                    mma_bf16(acc[mi][ni], al[mi], ph);
                }
        }
    }

    #pragma unroll
    for (int mi = 0; mi < 2; mi++) {
        int rr = row0 + wm * 32 + mi * 16 + g;
        #pragma unroll
        for (int ni = 0; ni < 6; ni++) {
            int n = wn * 48 + ni * 8 + l2 * 2;
            __nv_bfloat16* dh = (n < 64) ? g_qh : (n < 128) ? g_kh : g_vh;
            __nv_bfloat16* dl = (n < 64) ? g_ql : (n < 128) ? g_kl : g_vl;
            int col = n & 63;
            __nv_bfloat16 h0, l0, h1, l1, h2, l2b, h3, l3;
            split_bf(acc[mi][ni][0], h0, l0);
            split_bf(acc[mi][ni][1], h1, l1);
            split_bf(acc[mi][ni][2], h2, l2b);
            split_bf(acc[mi][ni][3], h3, l3);
            *(uint32_t*)(dh + rr * 64 + col)       = pk(h0, h1);
            *(uint32_t*)(dl + rr * 64 + col)       = pk(l0, l1);
            *(uint32_t*)(dh + (rr + 8) * 64 + col) = pk(h2, h3);
            *(uint32_t*)(dl + (rr + 8) * 64 + col) = pk(l2b, l3);
        }
    }
}

// ---------------------------------------------------------------------------
// attention with fused position term + WORK-PROPORTIONAL warp tiling.
// grid=(256,4), block=512. All 16 warps active in every mma phase.
// ---------------------------------------------------------------------------
__global__ __launch_bounds__(512, 1) void attn_kernel(float* __restrict__ out)
{
    extern __shared__ char smc[];
    float* sc = (float*)smc;                                   // 64*264 f32
    __nv_bfloat16* wh = (__nv_bfloat16*)(smc + 64 * 264 * 4);  // 64*264
    __nv_bfloat16* wl = wh + 64 * 264;
    __nv_bfloat16* qh = wl + 64 * 264;                         // 64*72
    __nv_bfloat16* ql = qh + 64 * 72;
    __nv_bfloat16* kh = ql + 64 * 72;                          // 256*72
    __nv_bfloat16* kl = kh + 256 * 72;

    const int b  = blockIdx.x;
    const int tt = 3 - blockIdx.y;          // heavy first
    const int t0 = tt * 64;
    const int nst = tt + 1;
    const int send = nst * 64;
    const int dlo = 192 - t0;
    const int tid = threadIdx.x, w = tid >> 5, lane = tid & 31;
    const int g = lane >> 2, l2 = lane & 3;

    const uint32_t qHa = smem_u32(qh), qLa = smem_u32(ql);
    const uint32_t kHa = smem_u32(kh), kLa = smem_u32(kl);
    const uint32_t wHa = smem_u32(wh), wLa = smem_u32(wl);

    // ---- phase A0: q/k copies + E half0 + sc init ----
    {
        int r = tid >> 3, c = (tid & 7) * 8;
        *(uint4*)(qh + r * 72 + c) = *(const uint4*)(g_qh + ((long)(b * Tn + t0 + r)) * 64 + c);
        *(uint4*)(ql + r * 72 + c) = *(const uint4*)(g_ql + ((long)(b * Tn + t0 + r)) * 64 + c);
    }
    for (int f = tid; f < send * 8; f += 512) {
        int r = f >> 3, c = (f & 7) * 8;
        *(uint4*)(kh + r * 72 + c) = *(const uint4*)(g_kh + ((long)(b * Tn + r)) * 64 + c);
        *(uint4*)(kl + r * 72 + c) = *(const uint4*)(g_kl + ((long)(b * Tn + r)) * 64 + c);
    }
    {
        int rows0 = send < 128 ? send : 128;
        for (int f = tid; f < rows0 * 8; f += 512) {
            int r = f >> 3, c = (f & 7) * 8;
            *(uint4*)(wh + r * 72 + c) = *(const uint4*)(g_Eh + (dlo + r) * 72 + c);
            *(uint4*)(wl + r * 72 + c) = *(const uint4*)(g_El + (dlo + r) * 72 + c);
        }
    }
    {
        const float4 neg = make_float4(-1e30f, -1e30f, -1e30f, -1e30f);
        #pragma unroll
        for (int i = 0; i < 8; i++) {
            int f = tid + i * 512;
            int r = f >> 6, s4 = (f & 63) << 2;
            *(float4*)&sc[r * 264 + s4] = neg;
        }
    }
    __syncthreads();

    // ---- A fragments (q) shared by P and score phases ----
    const int wm = w >> 3, wn = w & 7;      // 2m x 8n
    const int arow = wm * 32 + (lane & 15);
    const int acol = (lane >> 4) * 8;

    // ---- phase P: position GEMM per d-half, proportional chunks ----
    {
        const int nhalf = (send + 127) >> 7;
        for (int hh = 0; hh < nhalf; hh++) {
            if (hh == 1) {
                __syncthreads();
                for (int f = tid; f < (send - 128) * 8; f += 512) {
                    int r = f >> 3, c = (f & 7) * 8;
                    *(uint4*)(wh + r * 72 + c) = *(const uint4*)(g_Eh + (dlo + 128 + r) * 72 + c);
                    *(uint4*)(wl + r * 72 + c) = *(const uint4*)(g_El + (dlo + 128 + r) * 72 + c);
                }
                __syncthreads();
            }
            int wcap = send - hh * 128;
            if (wcap > 128) wcap = 128;
            const int cw = wcap >> 3;           // per-warp width: 8 or 16
            const int n8 = cw >> 3;             // 1 or 2 chunks of 8
            const int cb = wn * cw;
            // skip tiles mapping entirely to s < 0 (only possible in half 0)
            if (!(hh == 0 && cb + cw + wm * 32 < 33)) {
                const int brow = cb + (lane & 7) + (lane >> 4) * 8;
                const int bcol = ((lane >> 3) & 1) * 8;
                float pacc[2][2][4] = {};
                #pragma unroll
                for (int ks = 0; ks < 4; ks++) {
                    uint32_t ah[2][4], al[2][4], bh[4], bl[4];
                    #pragma unroll
                    for (int mi = 0; mi < 2; mi++) {
                        uint32_t off = ((arow + mi * 16) * 72 + ks * 16 + acol) * 2;
                        ldsm4(ah[mi], qHa + off);
                        ldsm4(al[mi], qLa + off);
                    }
                    {
                        uint32_t off = (brow * 72 + ks * 16 + bcol) * 2;
                        ldsm4(bh, wHa + off);
                        ldsm4(bl, wLa + off);
                    }
                    #pragma unroll
                    for (int mi = 0; mi < 2; mi++)
                        for (int ni = 0; ni < n8; ni++) {
                            mma_bf16(pacc[mi][ni], ah[mi], &bh[ni * 2]);
                            mma_bf16(pacc[mi][ni], ah[mi], &bl[ni * 2]);
                            mma_bf16(pacc[mi][ni], al[mi], &bh[ni * 2]);
                        }
                }
                #pragma unroll
                for (int mi = 0; mi < 2; mi++)
                    for (int ni = 0; ni < n8; ni++)
                        #pragma unroll
                        for (int hf = 0; hf < 2; hf++) {
                            int row = wm * 32 + mi * 16 + g + hf * 8;
                            int s = hh * 128 + cb + ni * 8 + l2 * 2 + row - 63;
                            if (s >= 0)     sc[row * 264 + s]     = pacc[mi][ni][hf * 2];
                            if (s + 1 >= 0) sc[row * 264 + s + 1] = pacc[mi][ni][hf * 2 + 1];
                        }
            }
        }
    }
    __syncthreads();

    // ---- score phase: per-warp width nst*8, all warps active ----
    {
        const int cw = nst * 8;
        const int cb = wn * cw;
        if (cb <= t0 + wm * 32 + 31) {      // causal skip
            float acc[2][4][4] = {};
            #pragma unroll
            for (int ks = 0; ks < 4; ks++) {
                uint32_t ah[2][4], al[2][4];
                #pragma unroll
                for (int mi = 0; mi < 2; mi++) {
                    uint32_t off = ((arow + mi * 16) * 72 + ks * 16 + acol) * 2;
                    ldsm4(ah[mi], qHa + off);
                    ldsm4(al[mi], qLa + off);
                }
                for (int nb = 0; nb < nst; nb += 2) {
                    uint32_t bh[4], bl[4];
                    int brow = cb + nb * 8 + (lane & 7) + (lane >> 4) * 8;
                    uint32_t off = (brow * 72 + ks * 16 + ((lane >> 3) & 1) * 8) * 2;
                    ldsm4(bh, kHa + off);
                    ldsm4(bl, kLa + off);
                    int lim = nst - nb < 2 ? nst - nb : 2;
                    #pragma unroll
                    for (int mi = 0; mi < 2; mi++)
                        for (int ni = 0; ni < lim; ni++) {
                            mma_bf16(acc[mi][nb + ni], ah[mi], &bh[ni * 2]);
                            mma_bf16(acc[mi][nb + ni], ah[mi], &bl[ni * 2]);
                            mma_bf16(acc[mi][nb + ni], al[mi], &bh[ni * 2]);
                        }
                }
            }
            #pragma unroll
            for (int mi = 0; mi < 2; mi++)
                for (int ni = 0; ni < nst; ni++) {
                    int rloc = wm * 32 + mi * 16 + g;
                    int sbase = cb + ni * 8 + l2 * 2;
                    #pragma unroll
                    for (int hf = 0; hf < 2; hf++) {
                        int row = rloc + hf * 8;
                        float2 cur = *(float2*)&sc[row * 264 + sbase];
                        cur.x += acc[mi][ni][hf * 2];
                        cur.y += acc[mi][ni][hf * 2 + 1];
                        *(float2*)&sc[row * 264 + sbase] = cur;
                    }
                }
        }
    }
    __syncthreads();

    // ---- load live v rows into kh/kl ----
    for (int f = tid; f < send * 8; f += 512) {
        int r = f >> 3, c = (f & 7) * 8;
        *(uint4*)(kh + r * 72 + c) = *(const uint4*)(g_vh + ((long)(b * Tn + r)) * 64 + c);
        *(uint4*)(kl + r * 72 + c) = *(const uint4*)(g_vl + ((long)(b * Tn + r)) * 64 + c);
    }

    // ---- softmax: 16 warps x 4 rows, bf16 hi/lo weight emit ----
    for (int r = w * 4; r < w * 4 + 4; r++) {
        float m = -1e30f;
        for (int i = 0; i < nst; i++) {
            float2 v = *(const float2*)&sc[r * 264 + i * 64 + lane * 2];
            m = fmaxf(m, fmaxf(v.x, v.y));
        }
        #pragma unroll
        for (int o = 16; o; o >>= 1) m = fmaxf(m, __shfl_xor_sync(0xffffffffu, m, o));
        float sum = 0.f;
        for (int i = 0; i < nst; i++) {
            float2 v = *(const float2*)&sc[r * 264 + i * 64 + lane * 2];
            v.x = __expf(v.x - m);
            v.y = __expf(v.y - m);
            sum += v.x + v.y;
            *(float2*)&sc[r * 264 + i * 64 + lane * 2] = v;
        }
        #pragma unroll
        for (int o = 16; o; o >>= 1) sum += __shfl_xor_sync(0xffffffffu, sum, o);
        float inv = 1.0f / sum;
        for (int i = 0; i < nst; i++) {
            float2 e = *(const float2*)&sc[r * 264 + i * 64 + lane * 2];
            float w0 = e.x * inv, w1 = e.y * inv;
            __nv_bfloat16 h0, l0, h1, l1;
            split_bf(w0, h0, l0);
            split_bf(w1, h1, l1);
            *(uint32_t*)&wh[r * 264 + i * 64 + lane * 2] = pk(h0, h1);
            *(uint32_t*)&wl[r * 264 + i * 64 + lane * 2] = pk(l0, l1);
        }
    }
    __syncthreads();

    // ---- out = wei @ v : split-K, slice width nst*16, all warps active ----
    {
        const int wk = w & 3;
        const int wn2 = (w >> 2) & 1;
        const int wm2 = w >> 3;
        const int kbase = wk * nst * 16;
        const int arow2 = wm2 * 32 + (lane & 15);
        const int acol2 = (lane >> 4) * 8;
        const int vrow = (lane & 7) + ((lane >> 3) & 1) * 8;
        const int vcol = wn2 * 32 + (lane >> 4) * 8;
        float oacc[2][4][4] = {};
        for (int ksi = 0; ksi < nst; ksi++) {
            const int koff = kbase + ksi * 16;
            uint32_t aw[2][4], awl[2][4], bvh[2][4], bvl[2][4];
            #pragma unroll
            for (int mi = 0; mi < 2; mi++) {
                uint32_t aoff = ((arow2 + mi * 16) * 264 + koff + acol2) * 2;
                ldsm4(aw[mi],  wHa + aoff);
                ldsm4(awl[mi], wLa + aoff);
            }
            #pragma unroll
            for (int nj = 0; nj < 2; nj++) {
                uint32_t voff = ((koff + vrow) * 72 + vcol + nj * 16) * 2;
                ldsm4t(bvh[nj], kHa + voff);
                ldsm4t(bvl[nj], kLa + voff);
            }
            #pragma unroll
            for (int mi = 0; mi < 2; mi++)
                #pragma unroll
                for (int ni = 0; ni < 4; ni++) {
                    const uint32_t* ph = &bvh[ni >> 1][(ni & 1) * 2];
                    const uint32_t* pl = &bvl[ni >> 1][(ni & 1) * 2];
                    mma_bf16(oacc[mi][ni], aw[mi],  ph);
                    mma_bf16(oacc[mi][ni], aw[mi],  pl);
                    mma_bf16(oacc[mi][ni], awl[mi], ph);
                }
        }
        float* slice = sc + wk * 4096;
        #pragma unroll
        for (int mi = 0; mi < 2; mi++)
            #pragma unroll
            for (int ni = 0; ni < 4; ni++) {
                int row = wm2 * 32 + mi * 16 + g;
                int col = wn2 * 32 + ni * 8 + l2 * 2;
                float2 o0 = {oacc[mi][ni][0], oacc[mi][ni][1]};
                float2 o1 = {oacc[mi][ni][2], oacc[mi][ni][3]};
                *(float2*)&slice[row * 64 + col] = o0;
                *(float2*)&slice[(row + 8) * 64 + col] = o1;
            }
    }
    __syncthreads();

    // ---- reduce 4 slices and store ----
    #pragma unroll
    for (int i = 0; i < 8; i++) {
        int idx = tid + i * 512;
        float s = sc[idx] + sc[4096 + idx] + sc[8192 + idx] + sc[12288 + idx];
        int row = idx >> 6, col = idx & 63;
        out[((long)(b * Tn + t0 + row)) * Hn + col] = s;
    }
}

// ---------------------------------------------------------------------------
extern "C" void kernel_launch(void* const* d_in, const int* in_sizes, int n_in,
                              void* d_out, int out_size)
{
    const float* x  = (const float*)d_in[0];
    const float* Wk = (const float*)d_in[1];
    const float* Wq = (const float*)d_in[2];
    const float* Wv = (const float*)d_in[3];
    const float* E  = (const float*)d_in[4];
    float* out = (float*)d_out;

    setup_kernel<<<288, 256>>>(Wk, Wq, Wv, E);

    const int qkv_sm = (2 * 128 * 72 + 2 * 192 * 72) * (int)sizeof(__nv_bfloat16); // 92160
    cudaFuncSetAttribute(qkv_kernel, cudaFuncAttributeMaxDynamicSharedMemorySize, qkv_sm);
    qkv_kernel<<<Bn * Tn / 128, 512, qkv_sm>>>(x);

    const int attn_sm = 64 * 264 * 4 + 2 * 64 * 264 * 2 + 2 * 64 * 72 * 2
                      + 2 * 256 * 72 * 2;                                          // 227328
    cudaFuncSetAttribute(attn_kernel, cudaFuncAttributeMaxDynamicSharedMemorySize, attn_sm);
    attn_kernel<<<dim3(Bn, Tn / 64), 512, attn_sm>>>(out);
}